// round 1
// baseline (speedup 1.0000x reference)
#include <cuda_runtime.h>
#include <math.h>

#define SEQ   2048
#define NH    32
#define NKV   8
#define HD    128
#define BM    64
#define BN    64
#define SCALEF 0.08838834764831845f

#define QS_STRIDE 132
#define KT_STRIDE 65
#define PS_STRIDE 65

#define QS_OFF 0
#define KT_OFF (QS_OFF + BM * QS_STRIDE)    /* 8448  */
#define VS_OFF (KT_OFF + HD * KT_STRIDE)    /* +8320 */
#define PS_OFF (VS_OFF + BN * HD)           /* +8192 */
#define SMEM_FLOATS (PS_OFF + BM * PS_STRIDE)
#define SMEM_BYTES (SMEM_FLOATS * 4)

__global__ __launch_bounds__(256, 1)
void attn_fp32_kernel(const float* __restrict__ q,
                      const float* __restrict__ k,
                      const float* __restrict__ v,
                      float* __restrict__ out)
{
    extern __shared__ float sm[];
    float* QS = sm + QS_OFF;
    float* KT = sm + KT_OFF;
    float* VS = sm + VS_OFF;
    float* PS = sm + PS_OFF;

    const int tid = threadIdx.x;
    const int qt  = blockIdx.x;
    const int h   = blockIdx.y;
    const int hk  = h >> 2;          // GQA: 4 query heads per kv head
    const int q0  = qt * BM;

    const int tx = tid & 15;         // 16 col-groups
    const int ty = tid >> 4;         // 16 row-groups
    const int r0 = ty * 4;           // 4 rows per thread (same rows in both GEMMs)

    // ---- load Q tile (scaled by 1/sqrt(d)) into QS[row][d] ----
    {
        const float* qbase = q + (size_t)q0 * (NH * HD) + (size_t)h * HD;
        #pragma unroll
        for (int it = 0; it < 8; ++it) {
            int idx = tid + it * 256;          // 0..2047 float4 slots
            int r   = idx >> 5;                // 32 float4 per row
            int d4  = (idx & 31) << 2;
            float4 val = *(const float4*)(qbase + (size_t)r * (NH * HD) + d4);
            val.x *= SCALEF; val.y *= SCALEF; val.z *= SCALEF; val.w *= SCALEF;
            *(float4*)(QS + r * QS_STRIDE + d4) = val;
        }
    }

    float o[4][8];
    #pragma unroll
    for (int i = 0; i < 4; ++i)
        #pragma unroll
        for (int j = 0; j < 8; ++j) o[i][j] = 0.f;

    float m_i[4], l_i[4];
    #pragma unroll
    for (int i = 0; i < 4; ++i) { m_i[i] = -1e30f; l_i[i] = 0.f; }

    __syncthreads();

    for (int jt = 0; jt <= qt; ++jt) {
        const int j0 = jt * BN;

        // ---- load K (transposed) and V tiles ----
        {
            const float* kbase = k + (size_t)j0 * (NKV * HD) + (size_t)hk * HD;
            const float* vbase = v + (size_t)j0 * (NKV * HD) + (size_t)hk * HD;
            #pragma unroll
            for (int it = 0; it < 8; ++it) {
                int idx = tid + it * 256;
                int r   = idx >> 5;
                int d4  = (idx & 31) << 2;
                float4 kv = *(const float4*)(kbase + (size_t)r * (NKV * HD) + d4);
                KT[(d4 + 0) * KT_STRIDE + r] = kv.x;
                KT[(d4 + 1) * KT_STRIDE + r] = kv.y;
                KT[(d4 + 2) * KT_STRIDE + r] = kv.z;
                KT[(d4 + 3) * KT_STRIDE + r] = kv.w;
                float4 vv = *(const float4*)(vbase + (size_t)r * (NKV * HD) + d4);
                *(float4*)(VS + r * HD + d4) = vv;
            }
        }
        __syncthreads();

        // ---- S = Q K^T  (64x64x128, 4x4 per thread) ----
        float s[4][4];
        #pragma unroll
        for (int i = 0; i < 4; ++i)
            #pragma unroll
            for (int j = 0; j < 4; ++j) s[i][j] = 0.f;

        const int c4 = tx * 4;
        #pragma unroll 4
        for (int d = 0; d < HD; ++d) {
            float a0 = QS[(r0 + 0) * QS_STRIDE + d];
            float a1 = QS[(r0 + 1) * QS_STRIDE + d];
            float a2 = QS[(r0 + 2) * QS_STRIDE + d];
            float a3 = QS[(r0 + 3) * QS_STRIDE + d];
            float b0 = KT[d * KT_STRIDE + c4 + 0];
            float b1 = KT[d * KT_STRIDE + c4 + 1];
            float b2 = KT[d * KT_STRIDE + c4 + 2];
            float b3 = KT[d * KT_STRIDE + c4 + 3];
            s[0][0] += a0 * b0; s[0][1] += a0 * b1; s[0][2] += a0 * b2; s[0][3] += a0 * b3;
            s[1][0] += a1 * b0; s[1][1] += a1 * b1; s[1][2] += a1 * b2; s[1][3] += a1 * b3;
            s[2][0] += a2 * b0; s[2][1] += a2 * b1; s[2][2] += a2 * b2; s[2][3] += a2 * b3;
            s[3][0] += a3 * b0; s[3][1] += a3 * b1; s[3][2] += a3 * b2; s[3][3] += a3 * b3;
        }

        // ---- causal mask (only needed on the diagonal tile) ----
        if (jt == qt) {
            #pragma unroll
            for (int i = 0; i < 4; ++i)
                #pragma unroll
                for (int j = 0; j < 4; ++j)
                    if (c4 + j > r0 + i) s[i][j] = -1e30f;
        }

        // ---- online softmax; row stats stay in registers ----
        float alpha[4];
        #pragma unroll
        for (int i = 0; i < 4; ++i) {
            float mx = fmaxf(fmaxf(s[i][0], s[i][1]), fmaxf(s[i][2], s[i][3]));
            #pragma unroll
            for (int off = 8; off > 0; off >>= 1)
                mx = fmaxf(mx, __shfl_xor_sync(0xffffffffu, mx, off));
            float mnew = fmaxf(m_i[i], mx);
            alpha[i] = __expf(m_i[i] - mnew);
            m_i[i] = mnew;
            float sum = 0.f;
            #pragma unroll
            for (int j = 0; j < 4; ++j) {
                float p = __expf(s[i][j] - mnew);
                s[i][j] = p;
                sum += p;
            }
            #pragma unroll
            for (int off = 8; off > 0; off >>= 1)
                sum += __shfl_xor_sync(0xffffffffu, sum, off);
            l_i[i] = l_i[i] * alpha[i] + sum;

            PS[(r0 + i) * PS_STRIDE + c4 + 0] = s[i][0];
            PS[(r0 + i) * PS_STRIDE + c4 + 1] = s[i][1];
            PS[(r0 + i) * PS_STRIDE + c4 + 2] = s[i][2];
            PS[(r0 + i) * PS_STRIDE + c4 + 3] = s[i][3];
        }
        __syncthreads();

        // ---- O = O*alpha + P @ V   (64x128x64, 4x8 per thread) ----
        #pragma unroll
        for (int i = 0; i < 4; ++i)
            #pragma unroll
            for (int j = 0; j < 8; ++j) o[i][j] *= alpha[i];

        const int c8 = tx * 8;
        #pragma unroll 2
        for (int kk = 0; kk < BN; ++kk) {
            float a0 = PS[(r0 + 0) * PS_STRIDE + kk];
            float a1 = PS[(r0 + 1) * PS_STRIDE + kk];
            float a2 = PS[(r0 + 2) * PS_STRIDE + kk];
            float a3 = PS[(r0 + 3) * PS_STRIDE + kk];
            float4 b0 = *(const float4*)(VS + kk * HD + c8);
            float4 b1 = *(const float4*)(VS + kk * HD + c8 + 4);
            o[0][0] += a0 * b0.x; o[0][1] += a0 * b0.y; o[0][2] += a0 * b0.z; o[0][3] += a0 * b0.w;
            o[0][4] += a0 * b1.x; o[0][5] += a0 * b1.y; o[0][6] += a0 * b1.z; o[0][7] += a0 * b1.w;
            o[1][0] += a1 * b0.x; o[1][1] += a1 * b0.y; o[1][2] += a1 * b0.z; o[1][3] += a1 * b0.w;
            o[1][4] += a1 * b1.x; o[1][5] += a1 * b1.y; o[1][6] += a1 * b1.z; o[1][7] += a1 * b1.w;
            o[2][0] += a2 * b0.x; o[2][1] += a2 * b0.y; o[2][2] += a2 * b0.z; o[2][3] += a2 * b0.w;
            o[2][4] += a2 * b1.x; o[2][5] += a2 * b1.y; o[2][6] += a2 * b1.z; o[2][7] += a2 * b1.w;
            o[3][0] += a3 * b0.x; o[3][1] += a3 * b0.y; o[3][2] += a3 * b0.z; o[3][3] += a3 * b0.w;
            o[3][4] += a3 * b1.x; o[3][5] += a3 * b1.y; o[3][6] += a3 * b1.z; o[3][7] += a3 * b1.w;
        }
        __syncthreads();
    }

    // ---- finalize: divide by l, write out ----
    {
        float* obase = out + (size_t)q0 * (NH * HD) + (size_t)h * HD;
        const int c8 = tx * 8;
        #pragma unroll
        for (int i = 0; i < 4; ++i) {
            float inv = 1.0f / l_i[i];
            float4 w0, w1;
            w0.x = o[i][0] * inv; w0.y = o[i][1] * inv; w0.z = o[i][2] * inv; w0.w = o[i][3] * inv;
            w1.x = o[i][4] * inv; w1.y = o[i][5] * inv; w1.z = o[i][6] * inv; w1.w = o[i][7] * inv;
            float* orow = obase + (size_t)(r0 + i) * (NH * HD) + c8;
            *(float4*)(orow)     = w0;
            *(float4*)(orow + 4) = w1;
        }
    }
}

extern "C" void kernel_launch(void* const* d_in, const int* in_sizes, int n_in,
                              void* d_out, int out_size)
{
    const float* q = (const float*)d_in[0];
    const float* k = (const float*)d_in[1];
    const float* v = (const float*)d_in[2];
    float* out = (float*)d_out;

    cudaFuncSetAttribute(attn_fp32_kernel,
                         cudaFuncAttributeMaxDynamicSharedMemorySize, SMEM_BYTES);

    dim3 grid(SEQ / BM, NH);
    attn_fp32_kernel<<<grid, 256, SMEM_BYTES>>>(q, k, v, out);
}

// round 3
// speedup vs baseline: 8.1321x; 8.1321x over previous
#include <cuda_runtime.h>
#include <cuda_fp16.h>
#include <cstdint>

#define SEQ   2048
#define NH    32
#define NKV   8
#define HD    128
#define BM    128
#define BN    64
#define QSTRIDE  (NH*HD)
#define KVSTRIDE (NKV*HD)
// scale * log2(e): softmax done in base-2 domain
#define QSCALE (0.08838834764831845f * 1.4426950408889634f)

#define SSTRIDE 136                     /* fp16 elems per smem row (128 + 8 pad) */
#define QS_OFF 0
#define KS_OFF (BM * SSTRIDE * 2)       /* 34816 */
#define VS_OFF (KS_OFF + BN * SSTRIDE * 2)
#define SMEM_BYTES (VS_OFF + BN * SSTRIDE * 2)   /* 69632 */

__device__ __forceinline__ uint32_t smem_u32(const void* p) {
    uint32_t a;
    asm("{ .reg .u64 t; cvta.to.shared.u64 t, %1; cvt.u32.u64 %0, t; }" : "=r"(a) : "l"(p));
    return a;
}

#define LDSM_X4(r0,r1,r2,r3,a) \
    asm volatile("ldmatrix.sync.aligned.m8n8.x4.shared.b16 {%0,%1,%2,%3}, [%4];" \
                 : "=r"(r0),"=r"(r1),"=r"(r2),"=r"(r3) : "r"(a))
#define LDSM_X4T(r0,r1,r2,r3,a) \
    asm volatile("ldmatrix.sync.aligned.m8n8.x4.trans.shared.b16 {%0,%1,%2,%3}, [%4];" \
                 : "=r"(r0),"=r"(r1),"=r"(r2),"=r"(r3) : "r"(a))

#define MMA16816(d, a, b0, b1) \
    asm volatile("mma.sync.aligned.m16n8k16.row.col.f32.f16.f16.f32 " \
                 "{%0,%1,%2,%3}, {%4,%5,%6,%7}, {%8,%9}, {%0,%1,%2,%3};" \
                 : "+f"((d)[0]),"+f"((d)[1]),"+f"((d)[2]),"+f"((d)[3]) \
                 : "r"((a)[0]),"r"((a)[1]),"r"((a)[2]),"r"((a)[3]),"r"(b0),"r"(b1))

__device__ __forceinline__ float ex2f(float x) {
    float r;
    asm("ex2.approx.ftz.f32 %0, %1;" : "=f"(r) : "f"(x));
    return r;
}
__device__ __forceinline__ uint32_t packh2(float a, float b) {
    __half2 h = __floats2half2_rn(a, b);
    return *(uint32_t*)&h;
}

__global__ __launch_bounds__(256, 1)
void attn_hmma_kernel(const float* __restrict__ q, const float* __restrict__ k,
                      const float* __restrict__ v, float* __restrict__ out)
{
    extern __shared__ char smem[];
    const uint32_t sb = smem_u32(smem);
    const int tid  = threadIdx.x;
    const int wid  = tid >> 5;
    const int lane = tid & 31;
    const int qt   = 15 - (int)blockIdx.x;        // long CTAs first
    const int h    = (int)blockIdx.y;
    const int hk   = h >> 2;
    const int q0   = qt * BM;
    const int NT   = 2 * qt + 2;                  // KV tiles of 64

    // ---- load Q (scaled, fp16) into SMEM ----
    {
        const float* qb = q + (size_t)q0 * QSTRIDE + (size_t)h * HD;
        #pragma unroll
        for (int it = 0; it < 16; ++it) {
            int idx = it * 256 + tid;             // 4096 float4 slots
            int r = idx >> 5, c4 = (idx & 31) << 2;
            float4 val = *(const float4*)(qb + (size_t)r * QSTRIDE + c4);
            uint2 hh;
            hh.x = packh2(val.x * QSCALE, val.y * QSCALE);
            hh.y = packh2(val.z * QSCALE, val.w * QSCALE);
            *(uint2*)(smem + QS_OFF + (r * SSTRIDE + c4) * 2) = hh;
        }
    }
    __syncthreads();

    // ---- Q A-fragments into registers (held for the whole kernel) ----
    uint32_t qa[8][4];
    {
        int row = wid * 16 + (lane & 15);
        #pragma unroll
        for (int ks = 0; ks < 8; ++ks) {
            uint32_t a = sb + QS_OFF + (row * SSTRIDE + ks * 16 + (lane >> 4) * 8) * 2;
            LDSM_X4(qa[ks][0], qa[ks][1], qa[ks][2], qa[ks][3], a);
        }
    }

    float oacc[16][4];
    #pragma unroll
    for (int i = 0; i < 16; ++i)
        #pragma unroll
        for (int j = 0; j < 4; ++j) oacc[i][j] = 0.f;
    float m0 = -1e30f, m1 = -1e30f, l0 = 0.f, l1 = 0.f;

    const int rr0 = q0 + wid * 16 + (lane >> 2);   // global row of accum slots 0,1
    const float* kb_head = k + (size_t)hk * HD;
    const float* vb_head = v + (size_t)hk * HD;

    for (int jt = 0; jt < NT; ++jt) {
        const int j0 = jt * BN;

        // ---- load K, V tiles (fp32 -> fp16 smem) ----
        {
            const float* kb = kb_head + (size_t)j0 * KVSTRIDE;
            const float* vb = vb_head + (size_t)j0 * KVSTRIDE;
            #pragma unroll
            for (int it = 0; it < 8; ++it) {
                int idx = it * 256 + tid;          // 2048 float4 slots
                int r = idx >> 5, c4 = (idx & 31) << 2;
                float4 kv = *(const float4*)(kb + (size_t)r * KVSTRIDE + c4);
                uint2 hk2;
                hk2.x = packh2(kv.x, kv.y);
                hk2.y = packh2(kv.z, kv.w);
                *(uint2*)(smem + KS_OFF + (r * SSTRIDE + c4) * 2) = hk2;
                float4 vv = *(const float4*)(vb + (size_t)r * KVSTRIDE + c4);
                uint2 hv2;
                hv2.x = packh2(vv.x, vv.y);
                hv2.y = packh2(vv.z, vv.w);
                *(uint2*)(smem + VS_OFF + (r * SSTRIDE + c4) * 2) = hv2;
            }
        }
        __syncthreads();

        // ---- S = Q @ K^T  (8 n-tiles x 8 k-steps) ----
        float sacc[8][4];
        #pragma unroll
        for (int i = 0; i < 8; ++i)
            #pragma unroll
            for (int j = 0; j < 4; ++j) sacc[i][j] = 0.f;

        #pragma unroll
        for (int nt = 0; nt < 8; ++nt) {
            uint32_t krow = sb + KS_OFF + ((nt * 8 + (lane & 7)) * SSTRIDE) * 2;
            #pragma unroll
            for (int kp = 0; kp < 4; ++kp) {
                uint32_t b0, b1, b2, b3;
                uint32_t a = krow + (kp * 32 + (lane >> 3) * 8) * 2;
                LDSM_X4(b0, b1, b2, b3, a);
                MMA16816(sacc[nt], qa[2 * kp],     b0, b1);
                MMA16816(sacc[nt], qa[2 * kp + 1], b2, b3);
            }
        }

        // ---- causal mask (only last two tiles touch the diagonal) ----
        if (jt >= NT - 2) {
            #pragma unroll
            for (int nt = 0; nt < 8; ++nt) {
                int jc = j0 + nt * 8 + ((lane & 3) << 1);
                if (jc     > rr0    ) sacc[nt][0] = -1e30f;
                if (jc + 1 > rr0    ) sacc[nt][1] = -1e30f;
                if (jc     > rr0 + 8) sacc[nt][2] = -1e30f;
                if (jc + 1 > rr0 + 8) sacc[nt][3] = -1e30f;
            }
        }

        // ---- online softmax (rows rr0, rr0+8; stats shared in quad) ----
        float mx0 = -1e30f, mx1 = -1e30f;
        #pragma unroll
        for (int nt = 0; nt < 8; ++nt) {
            mx0 = fmaxf(mx0, fmaxf(sacc[nt][0], sacc[nt][1]));
            mx1 = fmaxf(mx1, fmaxf(sacc[nt][2], sacc[nt][3]));
        }
        mx0 = fmaxf(mx0, __shfl_xor_sync(0xffffffffu, mx0, 1));
        mx0 = fmaxf(mx0, __shfl_xor_sync(0xffffffffu, mx0, 2));
        mx1 = fmaxf(mx1, __shfl_xor_sync(0xffffffffu, mx1, 1));
        mx1 = fmaxf(mx1, __shfl_xor_sync(0xffffffffu, mx1, 2));

        float mn0 = fmaxf(m0, mx0), mn1 = fmaxf(m1, mx1);
        float al0 = ex2f(m0 - mn0), al1 = ex2f(m1 - mn1);
        m0 = mn0; m1 = mn1;

        float sum0 = 0.f, sum1 = 0.f;
        #pragma unroll
        for (int nt = 0; nt < 8; ++nt) {
            sacc[nt][0] = ex2f(sacc[nt][0] - mn0);
            sacc[nt][1] = ex2f(sacc[nt][1] - mn0);
            sacc[nt][2] = ex2f(sacc[nt][2] - mn1);
            sacc[nt][3] = ex2f(sacc[nt][3] - mn1);
            sum0 += sacc[nt][0] + sacc[nt][1];
            sum1 += sacc[nt][2] + sacc[nt][3];
        }
        sum0 += __shfl_xor_sync(0xffffffffu, sum0, 1);
        sum0 += __shfl_xor_sync(0xffffffffu, sum0, 2);
        sum1 += __shfl_xor_sync(0xffffffffu, sum1, 1);
        sum1 += __shfl_xor_sync(0xffffffffu, sum1, 2);
        l0 = l0 * al0 + sum0;
        l1 = l1 * al1 + sum1;

        // ---- pack P into A-fragments (no SMEM round-trip) ----
        uint32_t pa[4][4];
        #pragma unroll
        for (int t = 0; t < 4; ++t) {
            pa[t][0] = packh2(sacc[2 * t][0],     sacc[2 * t][1]);
            pa[t][1] = packh2(sacc[2 * t][2],     sacc[2 * t][3]);
            pa[t][2] = packh2(sacc[2 * t + 1][0], sacc[2 * t + 1][1]);
            pa[t][3] = packh2(sacc[2 * t + 1][2], sacc[2 * t + 1][3]);
        }

        // ---- rescale O ----
        #pragma unroll
        for (int nt = 0; nt < 16; ++nt) {
            oacc[nt][0] *= al0; oacc[nt][1] *= al0;
            oacc[nt][2] *= al1; oacc[nt][3] *= al1;
        }

        // ---- O += P @ V  (16 d-tiles x 4 k-steps; V via ldmatrix.trans) ----
        #pragma unroll
        for (int dp = 0; dp < 8; ++dp) {
            #pragma unroll
            for (int kt = 0; kt < 4; ++kt) {
                uint32_t b0, b1, b2, b3;
                uint32_t a = sb + VS_OFF +
                    (((kt * 16) + (lane & 15)) * SSTRIDE + dp * 16 + (lane >> 4) * 8) * 2;
                LDSM_X4T(b0, b1, b2, b3, a);
                MMA16816(oacc[2 * dp],     pa[kt], b0, b1);
                MMA16816(oacc[2 * dp + 1], pa[kt], b2, b3);
            }
        }
        __syncthreads();
    }

    // ---- finalize: O / l, write fp32 out ----
    {
        float inv0 = 1.0f / l0, inv1 = 1.0f / l1;
        float* ob0 = out + (size_t)rr0 * QSTRIDE + (size_t)h * HD + ((lane & 3) << 1);
        float* ob1 = ob0 + 8 * QSTRIDE;
        #pragma unroll
        for (int nt = 0; nt < 16; ++nt) {
            float2 w0 = { oacc[nt][0] * inv0, oacc[nt][1] * inv0 };
            float2 w1 = { oacc[nt][2] * inv1, oacc[nt][3] * inv1 };
            *(float2*)(ob0 + nt * 8) = w0;
            *(float2*)(ob1 + nt * 8) = w1;
        }
    }
}

extern "C" void kernel_launch(void* const* d_in, const int* in_sizes, int n_in,
                              void* d_out, int out_size)
{
    const float* q = (const float*)d_in[0];
    const float* k = (const float*)d_in[1];
    const float* v = (const float*)d_in[2];
    float* out = (float*)d_out;

    cudaFuncSetAttribute(attn_hmma_kernel,
                         cudaFuncAttributeMaxDynamicSharedMemorySize, SMEM_BYTES);

    dim3 grid(SEQ / BM, NH);
    attn_hmma_kernel<<<grid, 256, SMEM_BYTES>>>(q, k, v, out);
}

// round 4
// speedup vs baseline: 8.9891x; 1.1054x over previous
#include <cuda_runtime.h>
#include <cuda_fp16.h>
#include <cstdint>

#define SEQ   2048
#define NH    32
#define NKV   8
#define HD    128
#define BM    128
#define BN    64
#define QSTRIDE  (NH*HD)
#define KVSTRIDE (NKV*HD)
// scale * log2(e): softmax done in base-2 domain
#define QSCALE (0.08838834764831845f * 1.4426950408889634f)

#define SSTRIDE 136                     /* fp16 elems per smem row (128 + 8 pad) */
#define QS_OFF 0
#define KS_OFF (BM * SSTRIDE * 2)       /* 34816 */
#define VS_OFF (KS_OFF + BN * SSTRIDE * 2)
#define SMEM_BYTES (VS_OFF + BN * SSTRIDE * 2)   /* 69632 */

__device__ __forceinline__ uint32_t smem_u32(const void* p) {
    uint32_t a;
    asm("{ .reg .u64 t; cvta.to.shared.u64 t, %1; cvt.u32.u64 %0, t; }" : "=r"(a) : "l"(p));
    return a;
}

#define LDSM_X4(r0,r1,r2,r3,a) \
    asm volatile("ldmatrix.sync.aligned.m8n8.x4.shared.b16 {%0,%1,%2,%3}, [%4];" \
                 : "=r"(r0),"=r"(r1),"=r"(r2),"=r"(r3) : "r"(a))
#define LDSM_X4T(r0,r1,r2,r3,a) \
    asm volatile("ldmatrix.sync.aligned.m8n8.x4.trans.shared.b16 {%0,%1,%2,%3}, [%4];" \
                 : "=r"(r0),"=r"(r1),"=r"(r2),"=r"(r3) : "r"(a))

#define MMA16816(d, a, b0, b1) \
    asm volatile("mma.sync.aligned.m16n8k16.row.col.f32.f16.f16.f32 " \
                 "{%0,%1,%2,%3}, {%4,%5,%6,%7}, {%8,%9}, {%0,%1,%2,%3};" \
                 : "+f"((d)[0]),"+f"((d)[1]),"+f"((d)[2]),"+f"((d)[3]) \
                 : "r"((a)[0]),"r"((a)[1]),"r"((a)[2]),"r"((a)[3]),"r"(b0),"r"(b1))

__device__ __forceinline__ float ex2f(float x) {
    float r;
    asm("ex2.approx.ftz.f32 %0, %1;" : "=f"(r) : "f"(x));
    return r;
}
__device__ __forceinline__ uint32_t packh2(float a, float b) {
    __half2 h = __floats2half2_rn(a, b);
    return *(uint32_t*)&h;
}

__global__ __launch_bounds__(256, 1)
void attn_hmma_kernel(const float* __restrict__ q, const float* __restrict__ k,
                      const float* __restrict__ v, float* __restrict__ out)
{
    extern __shared__ char smem[];
    const uint32_t sb = smem_u32(smem);
    const int tid  = threadIdx.x;
    const int wid  = tid >> 5;
    const int lane = tid & 31;
    const int qt   = 15 - (int)blockIdx.x;        // long CTAs first
    const int h    = (int)blockIdx.y;
    const int hk   = h >> 2;
    const int q0   = qt * BM;
    const int NT   = 2 * qt + 2;                  // KV tiles of 64

    // per-thread slot within a 64x128 fp32 tile (8 float4 slots)
    const int ldr  = tid >> 5;                    // rows 0..7 (+8 per it)
    const int ldc4 = (tid & 31) << 2;             // float4 col

    // ---- load Q (scaled, fp16) into SMEM ----
    {
        const float* qb = q + (size_t)q0 * QSTRIDE + (size_t)h * HD;
        #pragma unroll
        for (int it = 0; it < 16; ++it) {
            int idx = it * 256 + tid;
            int r = idx >> 5, c4 = (idx & 31) << 2;
            float4 val = *(const float4*)(qb + (size_t)r * QSTRIDE + c4);
            uint2 hh;
            hh.x = packh2(val.x * QSCALE, val.y * QSCALE);
            hh.y = packh2(val.z * QSCALE, val.w * QSCALE);
            *(uint2*)(smem + QS_OFF + (r * SSTRIDE + c4) * 2) = hh;
        }
    }
    __syncthreads();

    // ---- Q A-fragments into registers (held for the whole kernel) ----
    uint32_t qa[8][4];
    {
        int row = wid * 16 + (lane & 15);
        #pragma unroll
        for (int ks = 0; ks < 8; ++ks) {
            uint32_t a = sb + QS_OFF + (row * SSTRIDE + ks * 16 + (lane >> 4) * 8) * 2;
            LDSM_X4(qa[ks][0], qa[ks][1], qa[ks][2], qa[ks][3], a);
        }
    }

    float oacc[16][4];
    #pragma unroll
    for (int i = 0; i < 16; ++i)
        #pragma unroll
        for (int j = 0; j < 4; ++j) oacc[i][j] = 0.f;
    float m0 = -1e30f, m1 = -1e30f, l0 = 0.f, l1 = 0.f;

    const int rr0 = q0 + wid * 16 + (lane >> 2);
    const float* kb_head = k + (size_t)hk * HD + (size_t)ldr * KVSTRIDE + ldc4;
    const float* vb_head = v + (size_t)hk * HD + (size_t)ldr * KVSTRIDE + ldc4;

    float4 kreg[8], vreg[8];

    // ---- prologue: prefetch K tile 0 ----
    #pragma unroll
    for (int it = 0; it < 8; ++it)
        kreg[it] = *(const float4*)(kb_head + (size_t)it * 8 * KVSTRIDE);

    for (int jt = 0; jt < NT; ++jt) {
        const int j0 = jt * BN;

        // ---- commit K(jt) regs -> fp16 smem; prefetch V(jt) ----
        #pragma unroll
        for (int it = 0; it < 8; ++it) {
            uint2 hh;
            hh.x = packh2(kreg[it].x, kreg[it].y);
            hh.y = packh2(kreg[it].z, kreg[it].w);
            *(uint2*)(smem + KS_OFF + ((ldr + it * 8) * SSTRIDE + ldc4) * 2) = hh;
        }
        #pragma unroll
        for (int it = 0; it < 8; ++it)
            vreg[it] = *(const float4*)(vb_head + (size_t)(j0 + it * 8) * KVSTRIDE);
        __syncthreads();

        // ---- S = Q @ K^T  (8 n-tiles x 4 k-steps x 2) ----
        float sacc[8][4];
        #pragma unroll
        for (int i = 0; i < 8; ++i)
            #pragma unroll
            for (int j = 0; j < 4; ++j) sacc[i][j] = 0.f;

        #pragma unroll
        for (int nt = 0; nt < 8; ++nt) {
            uint32_t krow = sb + KS_OFF + ((nt * 8 + (lane & 7)) * SSTRIDE) * 2;
            #pragma unroll
            for (int kp = 0; kp < 4; ++kp) {
                uint32_t b0, b1, b2, b3;
                uint32_t a = krow + (kp * 32 + (lane >> 3) * 8) * 2;
                LDSM_X4(b0, b1, b2, b3, a);
                MMA16816(sacc[nt], qa[2 * kp],     b0, b1);
                MMA16816(sacc[nt], qa[2 * kp + 1], b2, b3);
            }
        }

        // ---- causal mask (only the last two tiles touch the diagonal) ----
        if (jt >= NT - 2) {
            #pragma unroll
            for (int nt = 0; nt < 8; ++nt) {
                int jc = j0 + nt * 8 + ((lane & 3) << 1);
                if (jc     > rr0    ) sacc[nt][0] = -1e30f;
                if (jc + 1 > rr0    ) sacc[nt][1] = -1e30f;
                if (jc     > rr0 + 8) sacc[nt][2] = -1e30f;
                if (jc + 1 > rr0 + 8) sacc[nt][3] = -1e30f;
            }
        }

        // ---- online softmax (rows rr0, rr0+8; stats shared in quad) ----
        float mx0 = -1e30f, mx1 = -1e30f;
        #pragma unroll
        for (int nt = 0; nt < 8; ++nt) {
            mx0 = fmaxf(mx0, fmaxf(sacc[nt][0], sacc[nt][1]));
            mx1 = fmaxf(mx1, fmaxf(sacc[nt][2], sacc[nt][3]));
        }
        mx0 = fmaxf(mx0, __shfl_xor_sync(0xffffffffu, mx0, 1));
        mx0 = fmaxf(mx0, __shfl_xor_sync(0xffffffffu, mx0, 2));
        mx1 = fmaxf(mx1, __shfl_xor_sync(0xffffffffu, mx1, 1));
        mx1 = fmaxf(mx1, __shfl_xor_sync(0xffffffffu, mx1, 2));

        float mn0 = fmaxf(m0, mx0), mn1 = fmaxf(m1, mx1);
        float al0 = ex2f(m0 - mn0), al1 = ex2f(m1 - mn1);
        m0 = mn0; m1 = mn1;

        float sum0 = 0.f, sum1 = 0.f;
        #pragma unroll
        for (int nt = 0; nt < 8; ++nt) {
            sacc[nt][0] = ex2f(sacc[nt][0] - mn0);
            sacc[nt][1] = ex2f(sacc[nt][1] - mn0);
            sacc[nt][2] = ex2f(sacc[nt][2] - mn1);
            sacc[nt][3] = ex2f(sacc[nt][3] - mn1);
            sum0 += sacc[nt][0] + sacc[nt][1];
            sum1 += sacc[nt][2] + sacc[nt][3];
        }
        sum0 += __shfl_xor_sync(0xffffffffu, sum0, 1);
        sum0 += __shfl_xor_sync(0xffffffffu, sum0, 2);
        sum1 += __shfl_xor_sync(0xffffffffu, sum1, 1);
        sum1 += __shfl_xor_sync(0xffffffffu, sum1, 2);
        l0 = l0 * al0 + sum0;
        l1 = l1 * al1 + sum1;

        // ---- pack P into A-fragments (no SMEM round-trip) ----
        uint32_t pa[4][4];
        #pragma unroll
        for (int t = 0; t < 4; ++t) {
            pa[t][0] = packh2(sacc[2 * t][0],     sacc[2 * t][1]);
            pa[t][1] = packh2(sacc[2 * t][2],     sacc[2 * t][3]);
            pa[t][2] = packh2(sacc[2 * t + 1][0], sacc[2 * t + 1][1]);
            pa[t][3] = packh2(sacc[2 * t + 1][2], sacc[2 * t + 1][3]);
        }

        // ---- commit V(jt) regs -> fp16 smem; prefetch K(jt+1) ----
        #pragma unroll
        for (int it = 0; it < 8; ++it) {
            uint2 hh;
            hh.x = packh2(vreg[it].x, vreg[it].y);
            hh.y = packh2(vreg[it].z, vreg[it].w);
            *(uint2*)(smem + VS_OFF + ((ldr + it * 8) * SSTRIDE + ldc4) * 2) = hh;
        }
        if (jt + 1 < NT) {
            #pragma unroll
            for (int it = 0; it < 8; ++it)
                kreg[it] = *(const float4*)(kb_head + (size_t)(j0 + BN + it * 8) * KVSTRIDE);
        }
        __syncthreads();

        // ---- rescale O ----
        #pragma unroll
        for (int nt = 0; nt < 16; ++nt) {
            oacc[nt][0] *= al0; oacc[nt][1] *= al0;
            oacc[nt][2] *= al1; oacc[nt][3] *= al1;
        }

        // ---- O += P @ V  (8 d-pairs x 4 k-steps; V via ldmatrix.trans) ----
        #pragma unroll
        for (int dp = 0; dp < 8; ++dp) {
            #pragma unroll
            for (int kt = 0; kt < 4; ++kt) {
                uint32_t b0, b1, b2, b3;
                uint32_t a = sb + VS_OFF +
                    (((kt * 16) + (lane & 15)) * SSTRIDE + dp * 16 + (lane >> 4) * 8) * 2;
                LDSM_X4T(b0, b1, b2, b3, a);
                MMA16816(oacc[2 * dp],     pa[kt], b0, b1);
                MMA16816(oacc[2 * dp + 1], pa[kt], b2, b3);
            }
        }
    }

    // ---- finalize: O / l, write fp32 out ----
    {
        float inv0 = 1.0f / l0, inv1 = 1.0f / l1;
        float* ob0 = out + (size_t)rr0 * QSTRIDE + (size_t)h * HD + ((lane & 3) << 1);
        float* ob1 = ob0 + 8 * QSTRIDE;
        #pragma unroll
        for (int nt = 0; nt < 16; ++nt) {
            float2 w0 = { oacc[nt][0] * inv0, oacc[nt][1] * inv0 };
            float2 w1 = { oacc[nt][2] * inv1, oacc[nt][3] * inv1 };
            *(float2*)(ob0 + nt * 8) = w0;
            *(float2*)(ob1 + nt * 8) = w1;
        }
    }
}

extern "C" void kernel_launch(void* const* d_in, const int* in_sizes, int n_in,
                              void* d_out, int out_size)
{
    const float* q = (const float*)d_in[0];
    const float* k = (const float*)d_in[1];
    const float* v = (const float*)d_in[2];
    float* out = (float*)d_out;

    cudaFuncSetAttribute(attn_hmma_kernel,
                         cudaFuncAttributeMaxDynamicSharedMemorySize, SMEM_BYTES);

    dim3 grid(SEQ / BM, NH);
    attn_hmma_kernel<<<grid, 256, SMEM_BYTES>>>(q, k, v, out);
}